// round 15
// baseline (speedup 1.0000x reference)
#include <cuda_runtime.h>
#include <cstdint>

// LSTMModelClassify: B=2048, T=512, D=1, H=50, C=2, 2-layer LSTM + FC.
// R15 = R14 + TRANSPOSED preact planes [batch][gate] (stride 201).
// R14's [gate][batch] planes made every MAC store ~7 wavefronts and every EW
// load ~9 wavefronts (stride-9 scatter) — ~45% of all crossbar traffic.
// Transposed: MAC stores hit consecutive gates (coalesced, ~1 wf), EW loads
// hit consecutive j (coalesced, ~2 wf). Everything else identical to R14.

#define TPB 256
constexpr int NB    = 7;
constexpr int Hh    = 50;
constexpr int G4    = 200;
constexpr int Tt    = 512;
constexpr int BATCH = 2048;
constexpr int NC    = 2;
constexpr int HS    = 52;    // weight/h row stride (50 + 2 zero pad)
constexpr int GS    = 201;   // plane batch stride (odd -> clean banks)

// shared memory layout (floats)
constexpr int OFF_WI1 = 0;                     // Wih1 [200][52]
constexpr int OFF_WH0 = OFF_WI1 + G4 * HS;     // Whh0 rows 100-199 [100][52]
constexpr int OFF_WH1 = OFF_WH0 + 100 * HS;    // Whh1 rows 100-199 [100][52]
constexpr int OFF_A   = OFF_WH1 + 100 * HS;    // h1 [7][52]
constexpr int OFF_B   = OFF_A   + NB * HS;     // h2 [7][52]
constexpr int OFF_P0  = OFF_B   + NB * HS;     // L1(t+1) preact [b][g]
constexpr int OFF_P1  = OFF_P0  + NB * GS;     // Whh1@h2(t-1) + bias1 [b][g]
constexpr int OFF_P2  = OFF_P1  + NB * GS;     // Wih1@h1(t) [b][g]
constexpr int OFF_BS0 = OFF_P2  + NB * GS;     // bias0 (bih0+bhh0) [200]
constexpr int OFF_WX  = OFF_BS0 + G4;          // Wih0 column [200]
constexpr int OFF_WFC = OFF_WX  + G4;
constexpr int OFF_BFC = OFF_WFC + NC * Hh;
constexpr int SMEMF   = OFF_BFC + NC;          // ~26.3K floats ≈ 105KB

__device__ __forceinline__ unsigned long long ffma2(unsigned long long a,
                                                    unsigned long long b,
                                                    unsigned long long c) {
    unsigned long long d;
    asm("fma.rn.f32x2 %0, %1, %2, %3;" : "=l"(d) : "l"(a), "l"(b), "l"(c));
    return d;
}

__device__ __forceinline__ float hadd2(unsigned long long a) {
    unsigned lo, hi;
    asm("mov.b64 {%0, %1}, %2;" : "=r"(lo), "=r"(hi) : "l"(a));
    return __uint_as_float(lo) + __uint_as_float(hi);
}

__device__ __forceinline__ float sigf(float x) {
    float e = __expf(-x);
    return __fdividef(1.0f, 1.0f + e);
}
__device__ __forceinline__ float tanh_(float x) {
    float e = __expf(2.0f * x);
    return 1.0f - __fdividef(2.0f, 1.0f + e);
}

__global__ void __launch_bounds__(TPB, 2) lstm_kernel(
    const float* __restrict__ x,
    const float* __restrict__ Wih0, const float* __restrict__ Whh0,
    const float* __restrict__ bih0, const float* __restrict__ bhh0,
    const float* __restrict__ Wih1, const float* __restrict__ Whh1,
    const float* __restrict__ bih1, const float* __restrict__ bhh1,
    const float* __restrict__ Wfc,  const float* __restrict__ bfc,
    float* __restrict__ out)
{
    extern __shared__ __align__(16) float sm[];
    const int tid = threadIdx.x;
    const int b0  = blockIdx.x * NB;

    for (int i = tid; i < SMEMF; i += TPB) sm[i] = 0.0f;   // zero: pads + h2 init
    __syncthreads();

    float* WI1  = sm + OFF_WI1;
    float* WH0  = sm + OFF_WH0;
    float* WH1  = sm + OFF_WH1;
    float* bufA = sm + OFF_A;
    float* bufB = sm + OFF_B;
    float* P0   = sm + OFF_P0;
    float* P1   = sm + OFF_P1;
    float* P2   = sm + OFF_P2;
    float* bs0s = sm + OFF_BS0;
    float* wxs  = sm + OFF_WX;
    float* wfc  = sm + OFF_WFC;
    float* bfcs = sm + OFF_BFC;

    // stage Wih1 (full), Whh0/Whh1 rows 100-199, bias0/wx, fc
    for (int i = tid; i < G4 * Hh; i += TPB) {
        int g = i / Hh, k = i % Hh;
        WI1[g * HS + k] = Wih1[i];
    }
    for (int i = tid; i < 100 * Hh; i += TPB) {
        int g = i / Hh, k = i % Hh;
        WH0[g * HS + k] = Whh0[(g + 100) * Hh + k];
        WH1[g * HS + k] = Whh1[(g + 100) * Hh + k];
    }
    for (int i = tid; i < G4; i += TPB) {
        bs0s[i] = bih0[i] + bhh0[i];
        wxs[i]  = Wih0[i];
    }
    for (int i = tid; i < NC * Hh; i += TPB) wfc[i] = Wfc[i];
    if (tid < NC) bfcs[tid] = bfc[tid];

    // ---- warp-aligned roles ----
    const int  warp  = tid >> 5;
    const int  lane  = tid & 31;
    const bool side1 = warp >= 4;                // 0: Whh0 side, 1: Whh1 side
    const int  wq    = warp & 3;
    const bool gact  = lane < 25;
    const int  s     = wq * 25 + (gact ? lane : 24);   // 0..99 (clamped dummies)

    // register weights: row s of Whh0 (side0) or Whh1 (side1)
    unsigned long long wreg[26];
    {
        const float* wsrc = side1 ? (Whh1 + s * Hh) : (Whh0 + s * Hh);
        const unsigned long long* ws = reinterpret_cast<const unsigned long long*>(wsrc);
#pragma unroll
        for (int i = 0; i < 25; ++i) wreg[i] = ws[i];
        wreg[25] = 0ULL;
    }
    const float* wsRow = (side1 ? WH1 : WH0) + s * HS;   // streamed row s+100

    float bA0, bA1, wxr0 = 0.f, wxr1 = 0.f;
    if (!side1) {
        bA0 = bih0[s] + bhh0[s];
        bA1 = bih0[s + 100] + bhh0[s + 100];
        wxr0 = Wih0[s];
        wxr1 = Wih0[s + 100];
    } else {
        bA0 = bih1[s] + bhh1[s];
        bA1 = bih1[s + 100] + bhh1[s + 100];
    }
    const float* hsrcA = side1 ? bufB : bufA;
    float*       plA   = side1 ? P1   : P0;

    // sweep-2 row of Wih1
    const int rB = side1 ? (s + 100) : s;
    const float* wrowB = WI1 + rB * HS;

    // x offsets (broadcast LDG; clamped for partial last block)
    int xoff[NB];
#pragma unroll
    for (int b = 0; b < NB; ++b) {
        int gb = b0 + b;
        xoff[b] = (gb < BATCH ? gb : BATCH - 1) * Tt;
    }

    // EW identity: u = tid, tid+256 (u<350); both layers per cell
    int  ewj[2], ewb[2], ewxo[2];
    bool ewok[2];
    float c1s[2] = {0.f, 0.f}, c2s[2] = {0.f, 0.f};
#pragma unroll
    for (int r = 0; r < 2; ++r) {
        int u = tid + TPB * r;
        ewok[r] = (u < Hh * NB);
        ewb[r] = u / Hh;
        ewj[r] = u % Hh;
        int gb = b0 + ewb[r];
        ewxo[r] = (gb < BATCH ? gb : BATCH - 1) * Tt;
    }

    __syncthreads();

    // ---- prologue: h1(0) = cell(Wih0*x(0) + bias0), c1 init; bufB=0, c2=0 ----
#pragma unroll
    for (int r = 0; r < 2; ++r) if (ewok[r]) {
        int j = ewj[r], b = ewb[r];
        float xv = __ldg(x + ewxo[r]);
        float pi = fmaf(wxs[j],        xv, bs0s[j]);
        float pf = fmaf(wxs[j + 50],   xv, bs0s[j + 50]);
        float pg = fmaf(wxs[j + 100],  xv, bs0s[j + 100]);
        float po = fmaf(wxs[j + 150],  xv, bs0s[j + 150]);
        float cc = sigf(pi) * tanh_(pg);           // f*c0 = 0
        c1s[r] = cc;
        bufA[b * HS + j] = sigf(po) * tanh_(cc);
    }
    __syncthreads();

    for (int t = 0; t < Tt; ++t) {
        const int txn = (t + 1 < Tt) ? (t + 1) : (Tt - 1);

        // ---- MAC sweep 1: recurrent rows (s reg, s+100 stream) @ h-state ----
        {
            unsigned long long a0[NB], a1[NB];
#pragma unroll
            for (int b = 0; b < NB; ++b) { a0[b] = 0ULL; a1[b] = 0ULL; }
#pragma unroll
            for (int k4 = 0; k4 < 13; ++k4) {
                ulonglong2 wv = *reinterpret_cast<const ulonglong2*>(wsRow + 4 * k4);
#pragma unroll
                for (int b = 0; b < NB; ++b) {
                    ulonglong2 hv = *reinterpret_cast<const ulonglong2*>(hsrcA + b * HS + 4 * k4);
                    a0[b] = ffma2(hv.x, wreg[2 * k4],     a0[b]);
                    a0[b] = ffma2(hv.y, wreg[2 * k4 + 1], a0[b]);
                    a1[b] = ffma2(hv.x, wv.x, a1[b]);
                    a1[b] = ffma2(hv.y, wv.y, a1[b]);
                }
            }
            if (gact) {
                if (!side1) {
#pragma unroll
                    for (int b = 0; b < NB; ++b) {
                        float xv = __ldg(x + xoff[b] + txn);
                        plA[b * GS + s]       = hadd2(a0[b]) + fmaf(wxr0, xv, bA0);
                        plA[b * GS + s + 100] = hadd2(a1[b]) + fmaf(wxr1, xv, bA1);
                    }
                } else {
#pragma unroll
                    for (int b = 0; b < NB; ++b) {
                        plA[b * GS + s]       = hadd2(a0[b]) + bA0;
                        plA[b * GS + s + 100] = hadd2(a1[b]) + bA1;
                    }
                }
            }
        }

        // ---- MAC sweep 2: Wih1[rB] @ h1(t) -> P2 (no barrier needed) ----
        {
            unsigned long long a[NB];
#pragma unroll
            for (int b = 0; b < NB; ++b) a[b] = 0ULL;
#pragma unroll
            for (int k4 = 0; k4 < 13; ++k4) {
                ulonglong2 wv = *reinterpret_cast<const ulonglong2*>(wrowB + 4 * k4);
#pragma unroll
                for (int b = 0; b < NB; ++b) {
                    ulonglong2 hv = *reinterpret_cast<const ulonglong2*>(bufA + b * HS + 4 * k4);
                    a[b] = ffma2(hv.x, wv.x, a[b]);
                    a[b] = ffma2(hv.y, wv.y, a[b]);
                }
            }
            if (gact) {
#pragma unroll
                for (int b = 0; b < NB; ++b) P2[b * GS + rB] = hadd2(a[b]);
            }
        }
        __syncthreads();

        // ---- EW: h2(t) from P1+P2; h1(t+1) from P0 (coalesced plane reads) ----
#pragma unroll
        for (int r = 0; r < 2; ++r) if (ewok[r]) {
            int j = ewj[r], b = ewb[r];
            const float* p1b = P1 + b * GS + j;
            const float* p2b = P2 + b * GS + j;
            const float* p0b = P0 + b * GS + j;
            // layer 2 at t
            {
                float pi = p1b[0]   + p2b[0];
                float pf = p1b[50]  + p2b[50];
                float pg = p1b[100] + p2b[100];
                float po = p1b[150] + p2b[150];
                float cc = sigf(pf) * c2s[r] + sigf(pi) * tanh_(pg);
                c2s[r] = cc;
                bufB[b * HS + j] = sigf(po) * tanh_(cc);
            }
            // layer 1 at t+1
            {
                float pi = p0b[0];
                float pf = p0b[50];
                float pg = p0b[100];
                float po = p0b[150];
                float cc = sigf(pf) * c1s[r] + sigf(pi) * tanh_(pg);
                c1s[r] = cc;
                bufA[b * HS + j] = sigf(po) * tanh_(cc);
            }
        }
        __syncthreads();
    }

    // ---- Final FC on h2(511) ----
    if (tid < NB * NC) {
        int bl = tid >> 1;
        int c  = tid & 1;
        int gb = b0 + bl;
        if (gb < BATCH) {
            float sacc = bfcs[c];
#pragma unroll
            for (int j = 0; j < Hh; ++j) sacc += wfc[c * Hh + j] * bufB[bl * HS + j];
            out[gb * NC + c] = sacc;
        }
    }
}

extern "C" void kernel_launch(void* const* d_in, const int* in_sizes, int n_in,
                              void* d_out, int out_size) {
    const float* x    = (const float*)d_in[0];
    const float* Wih0 = (const float*)d_in[1];
    const float* Whh0 = (const float*)d_in[2];
    const float* bih0 = (const float*)d_in[3];
    const float* bhh0 = (const float*)d_in[4];
    const float* Wih1 = (const float*)d_in[5];
    const float* Whh1 = (const float*)d_in[6];
    const float* bih1 = (const float*)d_in[7];
    const float* bhh1 = (const float*)d_in[8];
    const float* Wfc  = (const float*)d_in[9];
    const float* bfc  = (const float*)d_in[10];
    float* out = (float*)d_out;

    const int smem_bytes = SMEMF * (int)sizeof(float);
    cudaFuncSetAttribute(lstm_kernel, cudaFuncAttributeMaxDynamicSharedMemorySize, smem_bytes);

    const int grid = (BATCH + NB - 1) / NB;   // 293 blocks, 2 per SM
    lstm_kernel<<<grid, TPB, smem_bytes>>>(x, Wih0, Whh0, bih0, bhh0,
                                           Wih1, Whh1, bih1, bhh1,
                                           Wfc, bfc, out);
}

// round 16
// speedup vs baseline: 1.1250x; 1.1250x over previous
#include <cuda_runtime.h>
#include <cstdint>

// LSTMModelClassify: B=2048, T=512, D=1, H=50, C=2, 2-layer LSTM + FC.
// R16 = R15 + FUSED side0 MAC: Whh0[s](reg) + Whh0[s+100](smem) + Wih1[s](smem)
// share ONE broadcast h1 load stream (G=3, one k4 loop) — R15 loaded the same
// h1(t) twice (sweep1 + sweep2). Saves 91 LDS instr+wf per side0 warp per step.
// Side1 (reads h2 then h1, different sources) unchanged. Everything else = R15.

#define TPB 256
constexpr int NB    = 7;
constexpr int Hh    = 50;
constexpr int G4    = 200;
constexpr int Tt    = 512;
constexpr int BATCH = 2048;
constexpr int NC    = 2;
constexpr int HS    = 52;    // weight/h row stride (50 + 2 zero pad)
constexpr int GS    = 201;   // plane batch stride (odd -> clean banks)

// shared memory layout (floats)
constexpr int OFF_WI1 = 0;                     // Wih1 [200][52]
constexpr int OFF_WH0 = OFF_WI1 + G4 * HS;     // Whh0 rows 100-199 [100][52]
constexpr int OFF_WH1 = OFF_WH0 + 100 * HS;    // Whh1 rows 100-199 [100][52]
constexpr int OFF_A   = OFF_WH1 + 100 * HS;    // h1 [7][52]
constexpr int OFF_B   = OFF_A   + NB * HS;     // h2 [7][52]
constexpr int OFF_P0  = OFF_B   + NB * HS;     // L1(t+1) preact [b][g]
constexpr int OFF_P1  = OFF_P0  + NB * GS;     // Whh1@h2(t-1) + bias1 [b][g]
constexpr int OFF_P2  = OFF_P1  + NB * GS;     // Wih1@h1(t) [b][g]
constexpr int OFF_BS0 = OFF_P2  + NB * GS;     // bias0 (bih0+bhh0) [200]
constexpr int OFF_WX  = OFF_BS0 + G4;          // Wih0 column [200]
constexpr int OFF_WFC = OFF_WX  + G4;
constexpr int OFF_BFC = OFF_WFC + NC * Hh;
constexpr int SMEMF   = OFF_BFC + NC;          // ~26.3K floats ≈ 105KB

__device__ __forceinline__ unsigned long long ffma2(unsigned long long a,
                                                    unsigned long long b,
                                                    unsigned long long c) {
    unsigned long long d;
    asm("fma.rn.f32x2 %0, %1, %2, %3;" : "=l"(d) : "l"(a), "l"(b), "l"(c));
    return d;
}

__device__ __forceinline__ float hadd2(unsigned long long a) {
    unsigned lo, hi;
    asm("mov.b64 {%0, %1}, %2;" : "=r"(lo), "=r"(hi) : "l"(a));
    return __uint_as_float(lo) + __uint_as_float(hi);
}

__device__ __forceinline__ float sigf(float x) {
    float e = __expf(-x);
    return __fdividef(1.0f, 1.0f + e);
}
__device__ __forceinline__ float tanh_(float x) {
    float e = __expf(2.0f * x);
    return 1.0f - __fdividef(2.0f, 1.0f + e);
}

__global__ void __launch_bounds__(TPB, 2) lstm_kernel(
    const float* __restrict__ x,
    const float* __restrict__ Wih0, const float* __restrict__ Whh0,
    const float* __restrict__ bih0, const float* __restrict__ bhh0,
    const float* __restrict__ Wih1, const float* __restrict__ Whh1,
    const float* __restrict__ bih1, const float* __restrict__ bhh1,
    const float* __restrict__ Wfc,  const float* __restrict__ bfc,
    float* __restrict__ out)
{
    extern __shared__ __align__(16) float sm[];
    const int tid = threadIdx.x;
    const int b0  = blockIdx.x * NB;

    for (int i = tid; i < SMEMF; i += TPB) sm[i] = 0.0f;   // zero: pads + h2 init
    __syncthreads();

    float* WI1  = sm + OFF_WI1;
    float* WH0  = sm + OFF_WH0;
    float* WH1  = sm + OFF_WH1;
    float* bufA = sm + OFF_A;
    float* bufB = sm + OFF_B;
    float* P0   = sm + OFF_P0;
    float* P1   = sm + OFF_P1;
    float* P2   = sm + OFF_P2;
    float* bs0s = sm + OFF_BS0;
    float* wxs  = sm + OFF_WX;
    float* wfc  = sm + OFF_WFC;
    float* bfcs = sm + OFF_BFC;

    // stage Wih1 (full), Whh0/Whh1 rows 100-199, bias0/wx, fc
    for (int i = tid; i < G4 * Hh; i += TPB) {
        int g = i / Hh, k = i % Hh;
        WI1[g * HS + k] = Wih1[i];
    }
    for (int i = tid; i < 100 * Hh; i += TPB) {
        int g = i / Hh, k = i % Hh;
        WH0[g * HS + k] = Whh0[(g + 100) * Hh + k];
        WH1[g * HS + k] = Whh1[(g + 100) * Hh + k];
    }
    for (int i = tid; i < G4; i += TPB) {
        bs0s[i] = bih0[i] + bhh0[i];
        wxs[i]  = Wih0[i];
    }
    for (int i = tid; i < NC * Hh; i += TPB) wfc[i] = Wfc[i];
    if (tid < NC) bfcs[tid] = bfc[tid];

    // ---- warp-aligned roles ----
    const int  warp  = tid >> 5;
    const int  lane  = tid & 31;
    const bool side1 = warp >= 4;                // 0: h1 side, 1: h2 side
    const int  wq    = warp & 3;
    const bool gact  = lane < 25;
    const int  s     = wq * 25 + (gact ? lane : 24);   // 0..99 (clamped dummies)

    // register weights: row s of Whh0 (side0) or Whh1 (side1)
    unsigned long long wreg[26];
    {
        const float* wsrc = side1 ? (Whh1 + s * Hh) : (Whh0 + s * Hh);
        const unsigned long long* ws = reinterpret_cast<const unsigned long long*>(wsrc);
#pragma unroll
        for (int i = 0; i < 25; ++i) wreg[i] = ws[i];
        wreg[25] = 0ULL;
    }
    const float* wsRow = (side1 ? WH1 : WH0) + s * HS;   // streamed row s+100

    float bA0, bA1, wxr0 = 0.f, wxr1 = 0.f;
    if (!side1) {
        bA0 = bih0[s] + bhh0[s];
        bA1 = bih0[s + 100] + bhh0[s + 100];
        wxr0 = Wih0[s];
        wxr1 = Wih0[s + 100];
    } else {
        bA0 = bih1[s] + bhh1[s];
        bA1 = bih1[s + 100] + bhh1[s + 100];
    }

    // Wih1 row handled by this thread: side0 -> s (fused loop); side1 -> s+100
    const int rB = side1 ? (s + 100) : s;
    const float* wrowB = WI1 + rB * HS;

    // x offsets (broadcast LDG; clamped for partial last block)
    int xoff[NB];
#pragma unroll
    for (int b = 0; b < NB; ++b) {
        int gb = b0 + b;
        xoff[b] = (gb < BATCH ? gb : BATCH - 1) * Tt;
    }

    // EW identity: u = tid, tid+256 (u<350); both layers per cell
    int  ewj[2], ewb[2], ewxo[2];
    bool ewok[2];
    float c1s[2] = {0.f, 0.f}, c2s[2] = {0.f, 0.f};
#pragma unroll
    for (int r = 0; r < 2; ++r) {
        int u = tid + TPB * r;
        ewok[r] = (u < Hh * NB);
        ewb[r] = u / Hh;
        ewj[r] = u % Hh;
        int gb = b0 + ewb[r];
        ewxo[r] = (gb < BATCH ? gb : BATCH - 1) * Tt;
    }

    __syncthreads();

    // ---- prologue: h1(0) = cell(Wih0*x(0) + bias0), c1 init; bufB=0, c2=0 ----
#pragma unroll
    for (int r = 0; r < 2; ++r) if (ewok[r]) {
        int j = ewj[r], b = ewb[r];
        float xv = __ldg(x + ewxo[r]);
        float pi = fmaf(wxs[j],        xv, bs0s[j]);
        float pf = fmaf(wxs[j + 50],   xv, bs0s[j + 50]);
        float pg = fmaf(wxs[j + 100],  xv, bs0s[j + 100]);
        float po = fmaf(wxs[j + 150],  xv, bs0s[j + 150]);
        float cc = sigf(pi) * tanh_(pg);           // f*c0 = 0
        c1s[r] = cc;
        bufA[b * HS + j] = sigf(po) * tanh_(cc);
    }
    __syncthreads();

    for (int t = 0; t < Tt; ++t) {
        const int txn = (t + 1 < Tt) ? (t + 1) : (Tt - 1);

        if (!side1) {
            // ---- side0 FUSED G=3: one h1(t) stream feeds Whh0[s](reg),
            //      Whh0[s+100](smem), Wih1[s](smem) ----
            unsigned long long a0[NB], a1[NB], a2[NB];
#pragma unroll
            for (int b = 0; b < NB; ++b) { a0[b] = 0ULL; a1[b] = 0ULL; a2[b] = 0ULL; }
#pragma unroll
            for (int k4 = 0; k4 < 13; ++k4) {
                ulonglong2 wv1 = *reinterpret_cast<const ulonglong2*>(wsRow + 4 * k4);
                ulonglong2 wv2 = *reinterpret_cast<const ulonglong2*>(wrowB + 4 * k4);
#pragma unroll
                for (int b = 0; b < NB; ++b) {
                    ulonglong2 hv = *reinterpret_cast<const ulonglong2*>(bufA + b * HS + 4 * k4);
                    a0[b] = ffma2(hv.x, wreg[2 * k4],     a0[b]);
                    a0[b] = ffma2(hv.y, wreg[2 * k4 + 1], a0[b]);
                    a1[b] = ffma2(hv.x, wv1.x, a1[b]);
                    a1[b] = ffma2(hv.y, wv1.y, a1[b]);
                    a2[b] = ffma2(hv.x, wv2.x, a2[b]);
                    a2[b] = ffma2(hv.y, wv2.y, a2[b]);
                }
            }
            if (gact) {
#pragma unroll
                for (int b = 0; b < NB; ++b) {
                    float xv = __ldg(x + xoff[b] + txn);
                    P0[b * GS + s]       = hadd2(a0[b]) + fmaf(wxr0, xv, bA0);
                    P0[b * GS + s + 100] = hadd2(a1[b]) + fmaf(wxr1, xv, bA1);
                    P2[b * GS + s]       = hadd2(a2[b]);
                }
            }
        } else {
            // ---- side1 sweep 1: Whh1 rows (s reg, s+100 smem) @ h2(t-1) ----
            {
                unsigned long long a0[NB], a1[NB];
#pragma unroll
                for (int b = 0; b < NB; ++b) { a0[b] = 0ULL; a1[b] = 0ULL; }
#pragma unroll
                for (int k4 = 0; k4 < 13; ++k4) {
                    ulonglong2 wv = *reinterpret_cast<const ulonglong2*>(wsRow + 4 * k4);
#pragma unroll
                    for (int b = 0; b < NB; ++b) {
                        ulonglong2 hv = *reinterpret_cast<const ulonglong2*>(bufB + b * HS + 4 * k4);
                        a0[b] = ffma2(hv.x, wreg[2 * k4],     a0[b]);
                        a0[b] = ffma2(hv.y, wreg[2 * k4 + 1], a0[b]);
                        a1[b] = ffma2(hv.x, wv.x, a1[b]);
                        a1[b] = ffma2(hv.y, wv.y, a1[b]);
                    }
                }
                if (gact) {
#pragma unroll
                    for (int b = 0; b < NB; ++b) {
                        P1[b * GS + s]       = hadd2(a0[b]) + bA0;
                        P1[b * GS + s + 100] = hadd2(a1[b]) + bA1;
                    }
                }
            }
            // ---- side1 sweep 2: Wih1[s+100] @ h1(t) -> P2 ----
            {
                unsigned long long a[NB];
#pragma unroll
                for (int b = 0; b < NB; ++b) a[b] = 0ULL;
#pragma unroll
                for (int k4 = 0; k4 < 13; ++k4) {
                    ulonglong2 wv = *reinterpret_cast<const ulonglong2*>(wrowB + 4 * k4);
#pragma unroll
                    for (int b = 0; b < NB; ++b) {
                        ulonglong2 hv = *reinterpret_cast<const ulonglong2*>(bufA + b * HS + 4 * k4);
                        a[b] = ffma2(hv.x, wv.x, a[b]);
                        a[b] = ffma2(hv.y, wv.y, a[b]);
                    }
                }
                if (gact) {
#pragma unroll
                    for (int b = 0; b < NB; ++b) P2[b * GS + rB] = hadd2(a[b]);
                }
            }
        }
        __syncthreads();

        // ---- EW: h2(t) from P1+P2; h1(t+1) from P0 (coalesced plane reads) ----
#pragma unroll
        for (int r = 0; r < 2; ++r) if (ewok[r]) {
            int j = ewj[r], b = ewb[r];
            const float* p1b = P1 + b * GS + j;
            const float* p2b = P2 + b * GS + j;
            const float* p0b = P0 + b * GS + j;
            // layer 2 at t
            {
                float pi = p1b[0]   + p2b[0];
                float pf = p1b[50]  + p2b[50];
                float pg = p1b[100] + p2b[100];
                float po = p1b[150] + p2b[150];
                float cc = sigf(pf) * c2s[r] + sigf(pi) * tanh_(pg);
                c2s[r] = cc;
                bufB[b * HS + j] = sigf(po) * tanh_(cc);
            }
            // layer 1 at t+1
            {
                float pi = p0b[0];
                float pf = p0b[50];
                float pg = p0b[100];
                float po = p0b[150];
                float cc = sigf(pf) * c1s[r] + sigf(pi) * tanh_(pg);
                c1s[r] = cc;
                bufA[b * HS + j] = sigf(po) * tanh_(cc);
            }
        }
        __syncthreads();
    }

    // ---- Final FC on h2(511) ----
    if (tid < NB * NC) {
        int bl = tid >> 1;
        int c  = tid & 1;
        int gb = b0 + bl;
        if (gb < BATCH) {
            float sacc = bfcs[c];
#pragma unroll
            for (int j = 0; j < Hh; ++j) sacc += wfc[c * Hh + j] * bufB[bl * HS + j];
            out[gb * NC + c] = sacc;
        }
    }
}

extern "C" void kernel_launch(void* const* d_in, const int* in_sizes, int n_in,
                              void* d_out, int out_size) {
    const float* x    = (const float*)d_in[0];
    const float* Wih0 = (const float*)d_in[1];
    const float* Whh0 = (const float*)d_in[2];
    const float* bih0 = (const float*)d_in[3];
    const float* bhh0 = (const float*)d_in[4];
    const float* Wih1 = (const float*)d_in[5];
    const float* Whh1 = (const float*)d_in[6];
    const float* bih1 = (const float*)d_in[7];
    const float* bhh1 = (const float*)d_in[8];
    const float* Wfc  = (const float*)d_in[9];
    const float* bfc  = (const float*)d_in[10];
    float* out = (float*)d_out;

    const int smem_bytes = SMEMF * (int)sizeof(float);
    cudaFuncSetAttribute(lstm_kernel, cudaFuncAttributeMaxDynamicSharedMemorySize, smem_bytes);

    const int grid = (BATCH + NB - 1) / NB;   // 293 blocks, 2 per SM
    lstm_kernel<<<grid, TPB, smem_bytes>>>(x, Wih0, Whh0, bih0, bhh0,
                                           Wih1, Whh1, bih1, bhh1,
                                           Wfc, bfc, out);
}